// round 11
// baseline (speedup 1.0000x reference)
#include <cuda_runtime.h>
#include <cuda_bf16.h>
#include <cstdint>

// out[b,a,f] = (a < M[b]) * relu( resid[b,a,:] @ w[:,f] + node[b,a,f] )
// B=4096, A=128, K=RF=128, F=128 fp32.
// mma.sync m16n8k16 bf16, 3-pass split D = Ah*Bh + Al*Bh + Ah*Bl (fp32 accum).
// 1024 thr/CTA (32 warps), warp = 16 rows x 32 cols.
// resid: double-buffered cp.async raw tile (pitch 560B). node: direct LDG epilogue.

#define A_DIM 128
#define F_DIM 128
#define K_DIM 128

#define RPITCH 560                 // 140 floats: row bank-starts all distinct
#define SM_R0  0
#define SM_R1  71680               // 128*560
#define SM_BH  143360
#define SM_BL  184320
#define SMEM_TOTAL 225280

__device__ __forceinline__ uint32_t smem_u32(const void* p) {
    uint32_t a;
    asm("{ .reg .u64 t; cvta.to.shared.u64 t, %1; cvt.u32.u64 %0, t; }" : "=r"(a) : "l"(p));
    return a;
}
__device__ __forceinline__ uint32_t pack2h(float x, float y) {
    __nv_bfloat162 p(__float2bfloat16(x), __float2bfloat16(y));
    return *(uint32_t*)&p;
}
__device__ __forceinline__ uint32_t pack2l(float x, float y) {
    __nv_bfloat16 hx = __float2bfloat16(x), hy = __float2bfloat16(y);
    __nv_bfloat162 p(__float2bfloat16(x - __bfloat162float(hx)),
                     __float2bfloat16(y - __bfloat162float(hy)));
    return *(uint32_t*)&p;
}

#define LDS128(r0, r1, r2, r3, addr) \
    asm volatile("ld.shared.v4.b32 {%0,%1,%2,%3}, [%4];" \
                 : "=r"(r0), "=r"(r1), "=r"(r2), "=r"(r3) : "r"(addr))
#define LDS64F(f0, f1, addr) \
    asm volatile("ld.shared.v2.f32 {%0,%1}, [%2];" : "=f"(f0), "=f"(f1) : "r"(addr))
#define CP_ASYNC16(dst, src) \
    asm volatile("cp.async.cg.shared.global [%0], [%1], 16;" :: "r"(dst), "l"(src))
#define CP_COMMIT() asm volatile("cp.async.commit_group;" ::: "memory")
#define CP_WAIT1()  asm volatile("cp.async.wait_group 1;" ::: "memory")

__device__ __forceinline__ void mma_bf16(float* c, const uint32_t* a,
                                         uint32_t b0, uint32_t b1) {
    asm volatile(
        "mma.sync.aligned.m16n8k16.row.col.f32.bf16.bf16.f32 "
        "{%0,%1,%2,%3}, {%4,%5,%6,%7}, {%8,%9}, {%0,%1,%2,%3};"
        : "+f"(c[0]), "+f"(c[1]), "+f"(c[2]), "+f"(c[3])
        : "r"(a[0]), "r"(a[1]), "r"(a[2]), "r"(a[3]), "r"(b0), "r"(b1));
}

__global__ __launch_bounds__(1024, 1)
void blockend_mma(const float* __restrict__ node,
                  const float* __restrict__ resid,
                  const float* __restrict__ w,
                  const int*   __restrict__ mol_i32,
                  float* __restrict__ out,
                  int B)
{
    extern __shared__ char sm[];
    const uint32_t smb = smem_u32(sm);
    const int t    = threadIdx.x;
    const int wid  = t >> 5;
    const int lane = t & 31;
    const int mb   = wid >> 2;     // warp m-block: rows mb*16 .. +15
    const int wc   = wid & 3;      // warp col quarter: cols wc*32 .. +31

    const bool is_i64 = (mol_i32[1] == 0);

    // ---- prologue: cp.async resid(first tile) into buf0 ----
    int p = 0;
    const int b0 = blockIdx.x;
    int M_cur = 0;
    if (b0 < B) {
        M_cur = is_i64 ? mol_i32[4 * b0] : mol_i32[2 * b0];
        const char* src = (const char*)(resid + (size_t)b0 * A_DIM * K_DIM);
        #pragma unroll
        for (int i = 0; i < 4; i++) {
            int idx = t + (i << 10);           // 16B chunk id, 0..4095
            int r   = idx >> 5;                // row (warp-uniform)
            if (r < M_cur)
                CP_ASYNC16(smb + SM_R0 + r * RPITCH + ((idx & 31) << 4),
                           src + ((size_t)idx << 4));
        }
        CP_COMMIT();
    }

    // ---- one-time: w split into padded fragment layout Bh/Bl (validated R8) ----
    {
        const float4* wsrc = (const float4*)w;
        #pragma unroll
        for (int i = 0; i < 4; i++) {
            int idx4 = t + (i << 10);
            int k  = idx4 >> 5;
            int n0 = (idx4 & 31) << 2;
            float4 v = wsrc[idx4];
            float xs[4] = {v.x, v.y, v.z, v.w};
            int ks  = k >> 4;
            int rs  = ((((k >> 3) & 1)) << 2) + ((k & 1) << 1);
            int kl  = (k & 7) >> 1;
            #pragma unroll
            for (int j = 0; j < 4; j++) {
                int n   = n0 + j;
                int ln  = ((n & 7) << 2) + kl;
                int off = (((ks << 1) + (n >> 6)) * 32 + ln) * 80
                        + (((n >> 3) & 7) << 3) + rs;
                float x = xs[j];
                __nv_bfloat16 h = __float2bfloat16(x);
                *(__nv_bfloat16*)(sm + SM_BH + off) = h;
                *(__nv_bfloat16*)(sm + SM_BL + off) =
                    __float2bfloat16(x - __bfloat162float(h));
            }
        }
    }

    for (int b = b0; b < B; b += gridDim.x) {
        const int M = M_cur;

        // ---- issue cp.async resid(next tile) into buf[p^1] ----
        const int bn = b + gridDim.x;
        int M_nxt = 0;
        if (bn < B) {
            M_nxt = is_i64 ? mol_i32[4 * bn] : mol_i32[2 * bn];
            const uint32_t dbase = smb + (p ? SM_R0 : SM_R1);
            const char* src = (const char*)(resid + (size_t)bn * A_DIM * K_DIM);
            #pragma unroll
            for (int i = 0; i < 4; i++) {
                int idx = t + (i << 10);
                int r   = idx >> 5;
                if (r < M_nxt)
                    CP_ASYNC16(dbase + r * RPITCH + ((idx & 31) << 4),
                               src + ((size_t)idx << 4));
            }
        }
        CP_COMMIT();               // always commit: keeps group accounting uniform

        CP_WAIT1();                // resid(t) arrived (groups complete in order)
        __syncthreads();

        // ---- compute: warp = 16 rows x 32 cols, A from smem raw buf ----
        const bool act = (mb << 4) < M;
        float c[4][4];
        #pragma unroll
        for (int nb = 0; nb < 4; nb++)
            #pragma unroll
            for (int i = 0; i < 4; i++) c[nb][i] = 0.f;

        if (act) {
            const int R0  = (mb << 4) + (lane >> 2);
            const uint32_t abase = smb + (p ? SM_R1 : SM_R0)
                                 + (uint32_t)R0 * RPITCH + (((uint32_t)lane & 3) << 3);
            // B row for this warp's quarter: rows (ks*2 + (wc>>1)), byte sub-off (wc&1)*32
            const uint32_t bbase = smb + SM_BH
                                 + (uint32_t)(((wc >> 1) << 5) + lane) * 80
                                 + ((uint32_t)(wc & 1) << 5);

            #pragma unroll
            for (int ks = 0; ks < 8; ks++) {
                // A: rows R0, R0+8 ; k = kl2 + 16ks and +8
                float a00x, a00y, a01x, a01y, a10x, a10y, a11x, a11y;
                const uint32_t ak = abase + ((uint32_t)ks << 6);
                LDS64F(a00x, a00y, ak);                       // (R0,   k)
                LDS64F(a01x, a01y, ak + 32);                  // (R0,   k+8)
                LDS64F(a10x, a10y, ak + 8 * RPITCH);          // (R0+8, k)
                LDS64F(a11x, a11y, ak + 8 * RPITCH + 32);     // (R0+8, k+8)

                // a-frag order: a0=(r,k) a1=(r+8,k) a2=(r,k+8) a3=(r+8,k+8)
                uint32_t ah[4], al[4];
                ah[0] = pack2h(a00x, a00y);
                ah[1] = pack2h(a10x, a10y);
                ah[2] = pack2h(a01x, a01y);
                ah[3] = pack2h(a11x, a11y);
                al[0] = pack2l(a00x, a00y);
                al[1] = pack2l(a10x, a10y);
                al[2] = pack2l(a01x, a01y);
                al[3] = pack2l(a11x, a11y);

                const uint32_t ba = bbase + (uint32_t)(ks << 1) * 32 * 80;
                uint32_t h0[4], h1[4];
                LDS128(h0[0], h0[1], h0[2], h0[3], ba);        // nb 0,1
                LDS128(h1[0], h1[1], h1[2], h1[3], ba + 16);   // nb 2,3
                mma_bf16(c[0], ah, h0[0], h0[1]);
                mma_bf16(c[0], al, h0[0], h0[1]);
                mma_bf16(c[1], ah, h0[2], h0[3]);
                mma_bf16(c[1], al, h0[2], h0[3]);
                mma_bf16(c[2], ah, h1[0], h1[1]);
                mma_bf16(c[2], al, h1[0], h1[1]);
                mma_bf16(c[3], ah, h1[2], h1[3]);
                mma_bf16(c[3], al, h1[2], h1[3]);

                uint32_t l0[4], l1[4];
                LDS128(l0[0], l0[1], l0[2], l0[3], ba + (SM_BL - SM_BH));
                LDS128(l1[0], l1[1], l1[2], l1[3], ba + (SM_BL - SM_BH) + 16);
                mma_bf16(c[0], ah, l0[0], l0[1]);
                mma_bf16(c[1], ah, l0[2], l0[3]);
                mma_bf16(c[2], ah, l1[0], l1[1]);
                mma_bf16(c[3], ah, l1[2], l1[3]);
            }
        }

        // ---- epilogue: + node (direct LDG), relu, row mask, store ----
        const float* nt = node + (size_t)b * A_DIM * F_DIM;
        float*       ot = out  + (size_t)b * A_DIM * F_DIM;
        const int rbase = (mb << 4) + (lane >> 2);
        const int cbase = (wc << 5) + ((lane & 3) << 1);
        #pragma unroll
        for (int half = 0; half < 2; half++) {
            int r  = rbase + (half << 3);
            bool on = r < M;
            int ci = half << 1;
            #pragma unroll
            for (int nb = 0; nb < 4; nb++) {
                int col = cbase + (nb << 3);
                float2 o;
                if (on) {
                    float2 nv = *(const float2*)(nt + r * F_DIM + col);
                    o.x = fmaxf(c[nb][ci]     + nv.x, 0.f);
                    o.y = fmaxf(c[nb][ci + 1] + nv.y, 0.f);
                } else {
                    o.x = 0.f; o.y = 0.f;
                }
                *(float2*)(ot + r * F_DIM + col) = o;
            }
        }
        __syncthreads();   // compute reads of buf[p] done before next overwrite

        p ^= 1;
        M_cur = M_nxt;
    }
}

extern "C" void kernel_launch(void* const* d_in, const int* in_sizes, int n_in,
                              void* d_out, int out_size) {
    // size-based input identification (robust to metadata ordering)
    const float* node = nullptr;
    const float* res  = nullptr;
    const void*  wptr = nullptr;
    const void*  mptr = nullptr;

    for (int i = 0; i < n_in; i++) {
        if (in_sizes[i] >= (1 << 20)) {
            if (!node) node = (const float*)d_in[i];
            else if (!res) res = (const float*)d_in[i];
        }
    }
    for (int i = 0; i < n_in; i++) {
        if (in_sizes[i] < (1 << 20)) {
            if (!wptr && in_sizes[i] == F_DIM * K_DIM) { wptr = d_in[i]; continue; }
            if (!mptr && d_in[i] != wptr) mptr = d_in[i];
        }
    }
    if (!node) node = (const float*)d_in[0];
    if (!res)  res  = (const float*)d_in[1];
    if (!wptr) wptr = d_in[2];
    if (!mptr) mptr = d_in[3];

    int B = 0;
    for (int i = 0; i < n_in; i++)
        if (in_sizes[i] >= (1 << 20)) { B = in_sizes[i] / (A_DIM * F_DIM); break; }
    if (!B) B = 4096;

    int dev = 0, sms = 148;
    cudaGetDevice(&dev);
    cudaDeviceGetAttribute(&sms, cudaDevAttrMultiProcessorCount, dev);
    cudaFuncSetAttribute(blockend_mma, cudaFuncAttributeMaxDynamicSharedMemorySize,
                         SMEM_TOTAL);

    int grid = sms < B ? sms : B;
    blockend_mma<<<grid, 1024, SMEM_TOTAL>>>(node, res, (const float*)wptr,
                                             (const int*)mptr, (float*)d_out, B);
}

// round 12
// speedup vs baseline: 1.0670x; 1.0670x over previous
#include <cuda_runtime.h>
#include <cuda_bf16.h>
#include <cstdint>

// out[b,a,f] = (a < M[b]) * relu( resid[b,a,:] @ w[:,f] + node[b,a,f] )
// B=4096, A=128, K=RF=128, F=128 fp32.
// mma.sync m16n8k16 bf16, 3-pass split D = Ah*Bh + Al*Bh + Ah*Bl (fp32 accum).
// 512 thr/CTA, warp = 16 rows x 64 cols. resid: double-buffered cp.async raw tile.
// A LDS pipelined one k-step ahead; B loaded per nb-pair to cap live regs.

#define A_DIM 128
#define F_DIM 128
#define K_DIM 128

#define RPITCH 560                 // 140 floats: row bank-starts all distinct
#define SM_R0  0
#define SM_R1  71680               // 128*560
#define SM_BH  143360
#define SM_BL  184320
#define SMEM_TOTAL 225280

__device__ __forceinline__ uint32_t smem_u32(const void* p) {
    uint32_t a;
    asm("{ .reg .u64 t; cvta.to.shared.u64 t, %1; cvt.u32.u64 %0, t; }" : "=r"(a) : "l"(p));
    return a;
}
__device__ __forceinline__ uint32_t pack2h(float x, float y) {
    __nv_bfloat162 p(__float2bfloat16(x), __float2bfloat16(y));
    return *(uint32_t*)&p;
}
__device__ __forceinline__ uint32_t pack2l(float x, float y) {
    __nv_bfloat16 hx = __float2bfloat16(x), hy = __float2bfloat16(y);
    __nv_bfloat162 p(__float2bfloat16(x - __bfloat162float(hx)),
                     __float2bfloat16(y - __bfloat162float(hy)));
    return *(uint32_t*)&p;
}

#define LDS128(r0, r1, r2, r3, addr) \
    asm volatile("ld.shared.v4.b32 {%0,%1,%2,%3}, [%4];" \
                 : "=r"(r0), "=r"(r1), "=r"(r2), "=r"(r3) : "r"(addr))
#define LDS64F(f0, f1, addr) \
    asm volatile("ld.shared.v2.f32 {%0,%1}, [%2];" : "=f"(f0), "=f"(f1) : "r"(addr))
#define CP_ASYNC16(dst, src) \
    asm volatile("cp.async.cg.shared.global [%0], [%1], 16;" :: "r"(dst), "l"(src))
#define CP_COMMIT() asm volatile("cp.async.commit_group;" ::: "memory")
#define CP_WAIT1()  asm volatile("cp.async.wait_group 1;" ::: "memory")

__device__ __forceinline__ void mma_bf16(float* c, const uint32_t* a,
                                         uint32_t b0, uint32_t b1) {
    asm volatile(
        "mma.sync.aligned.m16n8k16.row.col.f32.bf16.bf16.f32 "
        "{%0,%1,%2,%3}, {%4,%5,%6,%7}, {%8,%9}, {%0,%1,%2,%3};"
        : "+f"(c[0]), "+f"(c[1]), "+f"(c[2]), "+f"(c[3])
        : "r"(a[0]), "r"(a[1]), "r"(a[2]), "r"(a[3]), "r"(b0), "r"(b1));
}

__global__ __launch_bounds__(512, 1)
void blockend_mma(const float* __restrict__ node,
                  const float* __restrict__ resid,
                  const float* __restrict__ w,
                  const int*   __restrict__ mol_i32,
                  float* __restrict__ out,
                  int B)
{
    extern __shared__ char sm[];
    const uint32_t smb = smem_u32(sm);
    const int t    = threadIdx.x;
    const int wid  = t >> 5;
    const int lane = t & 31;
    const int mb   = wid >> 1;     // warp m-block: rows mb*16 .. +15
    const int wc   = wid & 1;      // warp col half: cols wc*64 .. +63

    const bool is_i64 = (mol_i32[1] == 0);

    // ---- prologue: cp.async resid(first tile) into buf0 ----
    int p = 0;
    const int b0 = blockIdx.x;
    int M_cur = 0;
    if (b0 < B) {
        M_cur = is_i64 ? mol_i32[4 * b0] : mol_i32[2 * b0];
        const char* src = (const char*)(resid + (size_t)b0 * A_DIM * K_DIM);
        #pragma unroll
        for (int i = 0; i < 8; i++) {
            int idx = t + (i << 9);            // 16B chunk id, 0..4095
            int r   = idx >> 5;                // row (warp-uniform)
            if (r < M_cur)
                CP_ASYNC16(smb + SM_R0 + r * RPITCH + ((idx & 31) << 4),
                           src + ((size_t)idx << 4));
        }
        CP_COMMIT();
    }

    // ---- one-time: w split into padded fragment layout Bh/Bl (validated R8) ----
    {
        const float4* wsrc = (const float4*)w;
        #pragma unroll
        for (int i = 0; i < 8; i++) {
            int idx4 = t + (i << 9);
            int k  = idx4 >> 5;
            int n0 = (idx4 & 31) << 2;
            float4 v = wsrc[idx4];
            float xs[4] = {v.x, v.y, v.z, v.w};
            int ks  = k >> 4;
            int rs  = ((((k >> 3) & 1)) << 2) + ((k & 1) << 1);
            int kl  = (k & 7) >> 1;
            #pragma unroll
            for (int j = 0; j < 4; j++) {
                int n   = n0 + j;
                int ln  = ((n & 7) << 2) + kl;
                int off = (((ks << 1) + (n >> 6)) * 32 + ln) * 80
                        + (((n >> 3) & 7) << 3) + rs;
                float x = xs[j];
                __nv_bfloat16 h = __float2bfloat16(x);
                *(__nv_bfloat16*)(sm + SM_BH + off) = h;
                *(__nv_bfloat16*)(sm + SM_BL + off) =
                    __float2bfloat16(x - __bfloat162float(h));
            }
        }
    }

    for (int b = b0; b < B; b += gridDim.x) {
        const int M = M_cur;

        // ---- issue cp.async resid(next tile) into buf[p^1] ----
        const int bn = b + gridDim.x;
        int M_nxt = 0;
        if (bn < B) {
            M_nxt = is_i64 ? mol_i32[4 * bn] : mol_i32[2 * bn];
            const uint32_t dbase = smb + (p ? SM_R0 : SM_R1);
            const char* src = (const char*)(resid + (size_t)bn * A_DIM * K_DIM);
            #pragma unroll
            for (int i = 0; i < 8; i++) {
                int idx = t + (i << 9);
                int r   = idx >> 5;
                if (r < M_nxt)
                    CP_ASYNC16(dbase + r * RPITCH + ((idx & 31) << 4),
                               src + ((size_t)idx << 4));
            }
        }
        CP_COMMIT();               // always commit: keeps group accounting uniform

        CP_WAIT1();                // resid(t) arrived (groups complete in order)
        __syncthreads();

        // ---- compute: warp = 16 rows x 64 cols, A from smem, pipelined 1 ks ----
        const bool act = (mb << 4) < M;
        float c[8][4];
        #pragma unroll
        for (int nb = 0; nb < 8; nb++)
            #pragma unroll
            for (int i = 0; i < 4; i++) c[nb][i] = 0.f;

        if (act) {
            const int R0  = (mb << 4) + (lane >> 2);
            const uint32_t abase = smb + (p ? SM_R1 : SM_R0)
                                 + (uint32_t)R0 * RPITCH + (((uint32_t)lane & 3) << 3);
            const uint32_t bbase = smb + SM_BH + (uint32_t)((wc << 5) + lane) * 80;

            float2 cur[4], nxt[4];
            LDS64F(cur[0].x, cur[0].y, abase);                     // (R0,   k)
            LDS64F(cur[1].x, cur[1].y, abase + 32);                // (R0,   k+8)
            LDS64F(cur[2].x, cur[2].y, abase + 8 * RPITCH);        // (R0+8, k)
            LDS64F(cur[3].x, cur[3].y, abase + 8 * RPITCH + 32);   // (R0+8, k+8)

            #pragma unroll
            for (int ks = 0; ks < 8; ks++) {
                // prefetch A for ks+1 (hidden behind this ks's mmas)
                if (ks < 7) {
                    const uint32_t an = abase + (((uint32_t)ks + 1) << 6);
                    LDS64F(nxt[0].x, nxt[0].y, an);
                    LDS64F(nxt[1].x, nxt[1].y, an + 32);
                    LDS64F(nxt[2].x, nxt[2].y, an + 8 * RPITCH);
                    LDS64F(nxt[3].x, nxt[3].y, an + 8 * RPITCH + 32);
                }

                // a-frag order: a0=(r,k) a1=(r+8,k) a2=(r,k+8) a3=(r+8,k+8)
                uint32_t ah[4], al[4];
                ah[0] = pack2h(cur[0].x, cur[0].y);
                ah[1] = pack2h(cur[2].x, cur[2].y);
                ah[2] = pack2h(cur[1].x, cur[1].y);
                ah[3] = pack2h(cur[3].x, cur[3].y);
                al[0] = pack2l(cur[0].x, cur[0].y);
                al[1] = pack2l(cur[2].x, cur[2].y);
                al[2] = pack2l(cur[1].x, cur[1].y);
                al[3] = pack2l(cur[3].x, cur[3].y);

                const uint32_t ba = bbase + (uint32_t)(ks << 1) * 32 * 80;
                #pragma unroll
                for (int j = 0; j < 4; j++) {          // nb pair j -> nb 2j, 2j+1
                    uint32_t h[4], l[4];
                    LDS128(h[0], h[1], h[2], h[3], ba + (j << 4));
                    LDS128(l[0], l[1], l[2], l[3], ba + (SM_BL - SM_BH) + (j << 4));
                    mma_bf16(c[2 * j],     ah, h[0], h[1]);
                    mma_bf16(c[2 * j],     al, h[0], h[1]);
                    mma_bf16(c[2 * j],     ah, l[0], l[1]);
                    mma_bf16(c[2 * j + 1], ah, h[2], h[3]);
                    mma_bf16(c[2 * j + 1], al, h[2], h[3]);
                    mma_bf16(c[2 * j + 1], ah, l[2], l[3]);
                }

                cur[0] = nxt[0]; cur[1] = nxt[1];
                cur[2] = nxt[2]; cur[3] = nxt[3];
            }
        }

        // ---- epilogue: + node (direct LDG), relu, row mask, store ----
        const float* nt = node + (size_t)b * A_DIM * F_DIM;
        float*       ot = out  + (size_t)b * A_DIM * F_DIM;
        const int rbase = (mb << 4) + (lane >> 2);
        const int cbase = (wc << 6) + ((lane & 3) << 1);
        #pragma unroll
        for (int half = 0; half < 2; half++) {
            int r  = rbase + (half << 3);
            bool on = r < M;
            int ci = half << 1;
            #pragma unroll
            for (int nb = 0; nb < 8; nb++) {
                int col = cbase + (nb << 3);
                float2 o;
                if (on) {
                    float2 nv = *(const float2*)(nt + r * F_DIM + col);
                    o.x = fmaxf(c[nb][ci]     + nv.x, 0.f);
                    o.y = fmaxf(c[nb][ci + 1] + nv.y, 0.f);
                } else {
                    o.x = 0.f; o.y = 0.f;
                }
                *(float2*)(ot + r * F_DIM + col) = o;
            }
        }
        __syncthreads();   // compute reads of buf[p] done before next overwrite

        p ^= 1;
        M_cur = M_nxt;
    }
}

extern "C" void kernel_launch(void* const* d_in, const int* in_sizes, int n_in,
                              void* d_out, int out_size) {
    // size-based input identification (robust to metadata ordering)
    const float* node = nullptr;
    const float* res  = nullptr;
    const void*  wptr = nullptr;
    const void*  mptr = nullptr;

    for (int i = 0; i < n_in; i++) {
        if (in_sizes[i] >= (1 << 20)) {
            if (!node) node = (const float*)d_in[i];
            else if (!res) res = (const float*)d_in[i];
        }
    }
    for (int i = 0; i < n_in; i++) {
        if (in_sizes[i] < (1 << 20)) {
            if (!wptr && in_sizes[i] == F_DIM * K_DIM) { wptr = d_in[i]; continue; }
            if (!mptr && d_in[i] != wptr) mptr = d_in[i];
        }
    }
    if (!node) node = (const float*)d_in[0];
    if (!res)  res  = (const float*)d_in[1];
    if (!wptr) wptr = d_in[2];
    if (!mptr) mptr = d_in[3];

    int B = 0;
    for (int i = 0; i < n_in; i++)
        if (in_sizes[i] >= (1 << 20)) { B = in_sizes[i] / (A_DIM * F_DIM); break; }
    if (!B) B = 4096;

    int dev = 0, sms = 148;
    cudaGetDevice(&dev);
    cudaDeviceGetAttribute(&sms, cudaDevAttrMultiProcessorCount, dev);
    cudaFuncSetAttribute(blockend_mma, cudaFuncAttributeMaxDynamicSharedMemorySize,
                         SMEM_TOTAL);

    int grid = sms < B ? sms : B;
    blockend_mma<<<grid, 512, SMEM_TOTAL>>>(node, res, (const float*)wptr,
                                            (const int*)mptr, (float*)d_out, B);
}

// round 13
// speedup vs baseline: 1.1350x; 1.0637x over previous
#include <cuda_runtime.h>
#include <cuda_bf16.h>
#include <cstdint>

// out[b,a,f] = (a < M[b]) * relu( resid[b,a,:] @ w[:,f] + node[b,a,f] )
// B=4096, A=128, K=RF=128, F=128 fp32.
// mma.sync m16n8k16 bf16, 3-pass split D = Ah*Bh + Al*Bh + Ah*Bl (fp32 accum).
// 512 thr/CTA. Adaptive warp tiling: mA=ceil(M/16) m-blocks x ncg col groups,
// ncg in {2,4,8} so ~all 16 warps stay busy regardless of M.
// resid: double-buffered cp.async raw tile. node: direct LDG epilogue.

#define A_DIM 128
#define F_DIM 128
#define K_DIM 128

#define RPITCH 560                 // 140 floats: row bank-starts all distinct
#define SM_R0  0
#define SM_R1  71680               // 128*560
#define SM_BH  143360
#define SM_BL  184320
#define SMEM_TOTAL 225280

__device__ __forceinline__ uint32_t smem_u32(const void* p) {
    uint32_t a;
    asm("{ .reg .u64 t; cvta.to.shared.u64 t, %1; cvt.u32.u64 %0, t; }" : "=r"(a) : "l"(p));
    return a;
}
__device__ __forceinline__ uint32_t pack2h(float x, float y) {
    __nv_bfloat162 p(__float2bfloat16(x), __float2bfloat16(y));
    return *(uint32_t*)&p;
}
__device__ __forceinline__ uint32_t pack2l(float x, float y) {
    __nv_bfloat16 hx = __float2bfloat16(x), hy = __float2bfloat16(y);
    __nv_bfloat162 p(__float2bfloat16(x - __bfloat162float(hx)),
                     __float2bfloat16(y - __bfloat162float(hy)));
    return *(uint32_t*)&p;
}

#define LDS128(r0, r1, r2, r3, addr) \
    asm volatile("ld.shared.v4.b32 {%0,%1,%2,%3}, [%4];" \
                 : "=r"(r0), "=r"(r1), "=r"(r2), "=r"(r3) : "r"(addr))
#define LDS64F(f0, f1, addr) \
    asm volatile("ld.shared.v2.f32 {%0,%1}, [%2];" : "=f"(f0), "=f"(f1) : "r"(addr))
#define CP_ASYNC16(dst, src) \
    asm volatile("cp.async.cg.shared.global [%0], [%1], 16;" :: "r"(dst), "l"(src))
#define CP_COMMIT() asm volatile("cp.async.commit_group;" ::: "memory")
#define CP_WAIT1()  asm volatile("cp.async.wait_group 1;" ::: "memory")

__device__ __forceinline__ void mma_bf16(float* c, const uint32_t* a,
                                         uint32_t b0, uint32_t b1) {
    asm volatile(
        "mma.sync.aligned.m16n8k16.row.col.f32.bf16.bf16.f32 "
        "{%0,%1,%2,%3}, {%4,%5,%6,%7}, {%8,%9}, {%0,%1,%2,%3};"
        : "+f"(c[0]), "+f"(c[1]), "+f"(c[2]), "+f"(c[3])
        : "r"(a[0]), "r"(a[1]), "r"(a[2]), "r"(a[3]), "r"(b0), "r"(b1));
}

// One warp computes + stores a 16-row x NBC*8-col unit.
template<int NBC>
__device__ __forceinline__ void unit_compute(
    uint32_t smb, uint32_t rbuf_off, int lane, int mb, int cq, int M,
    const float* __restrict__ nt, float* __restrict__ ot)
{
    float c[NBC][4];
    #pragma unroll
    for (int nb = 0; nb < NBC; nb++)
        #pragma unroll
        for (int i = 0; i < 4; i++) c[nb][i] = 0.f;

    const int R0 = (mb << 4) + (lane >> 2);
    const uint32_t abase = smb + rbuf_off
                         + (uint32_t)R0 * RPITCH + (((uint32_t)lane & 3) << 3);

    const int n0     = cq * (NBC * 8);
    const int n_half = n0 >> 6;
    const int nb0    = (n0 >> 3) & 7;
    const uint32_t bbase = smb + SM_BH
                         + (uint32_t)((n_half << 5) + lane) * 80 + (nb0 << 3);

    float2 cur[4], nxt[4];
    LDS64F(cur[0].x, cur[0].y, abase);                     // (R0,   k)
    LDS64F(cur[1].x, cur[1].y, abase + 32);                // (R0,   k+8)
    LDS64F(cur[2].x, cur[2].y, abase + 8 * RPITCH);        // (R0+8, k)
    LDS64F(cur[3].x, cur[3].y, abase + 8 * RPITCH + 32);   // (R0+8, k+8)

    #pragma unroll
    for (int ks = 0; ks < 8; ks++) {
        if (ks < 7) {
            const uint32_t an = abase + (((uint32_t)ks + 1) << 6);
            LDS64F(nxt[0].x, nxt[0].y, an);
            LDS64F(nxt[1].x, nxt[1].y, an + 32);
            LDS64F(nxt[2].x, nxt[2].y, an + 8 * RPITCH);
            LDS64F(nxt[3].x, nxt[3].y, an + 8 * RPITCH + 32);
        }

        // a-frag order: a0=(r,k) a1=(r+8,k) a2=(r,k+8) a3=(r+8,k+8)
        uint32_t ah[4], al[4];
        ah[0] = pack2h(cur[0].x, cur[0].y);
        ah[1] = pack2h(cur[2].x, cur[2].y);
        ah[2] = pack2h(cur[1].x, cur[1].y);
        ah[3] = pack2h(cur[3].x, cur[3].y);
        al[0] = pack2l(cur[0].x, cur[0].y);
        al[1] = pack2l(cur[2].x, cur[2].y);
        al[2] = pack2l(cur[1].x, cur[1].y);
        al[3] = pack2l(cur[3].x, cur[3].y);

        const uint32_t ba = bbase + (uint32_t)(ks << 1) * 32 * 80;
        #pragma unroll
        for (int jp = 0; jp < NBC / 2; jp++) {     // nb pair jp -> 2jp, 2jp+1
            uint32_t h[4], l[4];
            LDS128(h[0], h[1], h[2], h[3], ba + (jp << 4));
            LDS128(l[0], l[1], l[2], l[3], ba + (SM_BL - SM_BH) + (jp << 4));
            mma_bf16(c[2 * jp],     ah, h[0], h[1]);
            mma_bf16(c[2 * jp],     al, h[0], h[1]);
            mma_bf16(c[2 * jp],     ah, l[0], l[1]);
            mma_bf16(c[2 * jp + 1], ah, h[2], h[3]);
            mma_bf16(c[2 * jp + 1], al, h[2], h[3]);
            mma_bf16(c[2 * jp + 1], ah, l[2], l[3]);
        }

        cur[0] = nxt[0]; cur[1] = nxt[1];
        cur[2] = nxt[2]; cur[3] = nxt[3];
    }

    // epilogue for this unit: + node (direct LDG), relu, row mask, store
    const int rbase = (mb << 4) + (lane >> 2);
    const int cbase = n0 + ((lane & 3) << 1);
    #pragma unroll
    for (int half = 0; half < 2; half++) {
        int r  = rbase + (half << 3);
        bool on = r < M;
        int ci = half << 1;
        #pragma unroll
        for (int nb = 0; nb < NBC; nb++) {
            int col = cbase + (nb << 3);
            float2 o;
            if (on) {
                float2 nv = *(const float2*)(nt + r * F_DIM + col);
                o.x = fmaxf(c[nb][ci]     + nv.x, 0.f);
                o.y = fmaxf(c[nb][ci + 1] + nv.y, 0.f);
            } else {
                o.x = 0.f; o.y = 0.f;
            }
            *(float2*)(ot + r * F_DIM + col) = o;
        }
    }
}

__global__ __launch_bounds__(512, 1)
void blockend_mma(const float* __restrict__ node,
                  const float* __restrict__ resid,
                  const float* __restrict__ w,
                  const int*   __restrict__ mol_i32,
                  float* __restrict__ out,
                  int B)
{
    extern __shared__ char sm[];
    const uint32_t smb = smem_u32(sm);
    const int t    = threadIdx.x;
    const int wid  = t >> 5;
    const int lane = t & 31;

    const bool is_i64 = (mol_i32[1] == 0);

    // ---- prologue: cp.async resid(first tile) into buf0 ----
    int p = 0;
    const int b0 = blockIdx.x;
    int M_cur = 0;
    if (b0 < B) {
        M_cur = is_i64 ? mol_i32[4 * b0] : mol_i32[2 * b0];
        const char* src = (const char*)(resid + (size_t)b0 * A_DIM * K_DIM);
        #pragma unroll
        for (int i = 0; i < 8; i++) {
            int idx = t + (i << 9);            // 16B chunk id, 0..4095
            int r   = idx >> 5;                // row (warp-uniform)
            if (r < M_cur)
                CP_ASYNC16(smb + SM_R0 + r * RPITCH + ((idx & 31) << 4),
                           src + ((size_t)idx << 4));
        }
        CP_COMMIT();
    }

    // ---- one-time: w split into padded fragment layout Bh/Bl (validated R8) ----
    {
        const float4* wsrc = (const float4*)w;
        #pragma unroll
        for (int i = 0; i < 8; i++) {
            int idx4 = t + (i << 9);
            int k  = idx4 >> 5;
            int n0 = (idx4 & 31) << 2;
            float4 v = wsrc[idx4];
            float xs[4] = {v.x, v.y, v.z, v.w};
            int ks  = k >> 4;
            int rs  = ((((k >> 3) & 1)) << 2) + ((k & 1) << 1);
            int kl  = (k & 7) >> 1;
            #pragma unroll
            for (int j = 0; j < 4; j++) {
                int n   = n0 + j;
                int ln  = ((n & 7) << 2) + kl;
                int off = (((ks << 1) + (n >> 6)) * 32 + ln) * 80
                        + (((n >> 3) & 7) << 3) + rs;
                float x = xs[j];
                __nv_bfloat16 h = __float2bfloat16(x);
                *(__nv_bfloat16*)(sm + SM_BH + off) = h;
                *(__nv_bfloat16*)(sm + SM_BL + off) =
                    __float2bfloat16(x - __bfloat162float(h));
            }
        }
    }

    for (int b = b0; b < B; b += gridDim.x) {
        const int M = M_cur;

        // ---- issue cp.async resid(next tile) into buf[p^1] ----
        const int bn = b + gridDim.x;
        int M_nxt = 0;
        if (bn < B) {
            M_nxt = is_i64 ? mol_i32[4 * bn] : mol_i32[2 * bn];
            const uint32_t dbase = smb + (p ? SM_R0 : SM_R1);
            const char* src = (const char*)(resid + (size_t)bn * A_DIM * K_DIM);
            #pragma unroll
            for (int i = 0; i < 8; i++) {
                int idx = t + (i << 9);
                int r   = idx >> 5;
                if (r < M_nxt)
                    CP_ASYNC16(dbase + r * RPITCH + ((idx & 31) << 4),
                               src + ((size_t)idx << 4));
            }
        }
        CP_COMMIT();               // always commit: keeps group accounting uniform

        CP_WAIT1();                // resid(t) arrived
        __syncthreads();

        // ---- adaptive warp tiling ----
        const int mA = (M + 15) >> 4;          // active m-blocks, 1..8
        const uint32_t rbuf = p ? SM_R1 : SM_R0;
        const float* nt = node + (size_t)b * A_DIM * F_DIM;
        float*       ot = out  + (size_t)b * A_DIM * F_DIM;

        if (mA > 4) {             // ncg=2, NBC=8  (units = 2*mA <= 16)
            if (wid < 2 * mA)
                unit_compute<8>(smb, rbuf, lane, wid >> 1, wid & 1, M, nt, ot);
        } else if (mA > 2) {      // ncg=4, NBC=4  (units = 4*mA <= 16)
            if (wid < 4 * mA)
                unit_compute<4>(smb, rbuf, lane, wid >> 2, wid & 3, M, nt, ot);
        } else {                  // ncg=8, NBC=2  (units = 8*mA <= 16)
            if (wid < 8 * mA)
                unit_compute<2>(smb, rbuf, lane, wid >> 3, wid & 7, M, nt, ot);
        }

        // ---- cooperative zero-fill of rows >= mA*16 ----
        {
            const int zr0 = mA << 4;
            const int n4  = (A_DIM - zr0) << 5;       // float4 count
            float4 z = make_float4(0.f, 0.f, 0.f, 0.f);
            float4* oz = (float4*)(ot + zr0 * F_DIM);
            for (int idx = t; idx < n4; idx += 512)
                oz[idx] = z;
        }
        __syncthreads();   // compute reads of buf[p] done before next overwrite

        p ^= 1;
        M_cur = M_nxt;
    }
}

extern "C" void kernel_launch(void* const* d_in, const int* in_sizes, int n_in,
                              void* d_out, int out_size) {
    // size-based input identification (robust to metadata ordering)
    const float* node = nullptr;
    const float* res  = nullptr;
    const void*  wptr = nullptr;
    const void*  mptr = nullptr;

    for (int i = 0; i < n_in; i++) {
        if (in_sizes[i] >= (1 << 20)) {
            if (!node) node = (const float*)d_in[i];
            else if (!res) res = (const float*)d_in[i];
        }
    }
    for (int i = 0; i < n_in; i++) {
        if (in_sizes[i] < (1 << 20)) {
            if (!wptr && in_sizes[i] == F_DIM * K_DIM) { wptr = d_in[i]; continue; }
            if (!mptr && d_in[i] != wptr) mptr = d_in[i];
        }
    }
    if (!node) node = (const float*)d_in[0];
    if (!res)  res  = (const float*)d_in[1];
    if (!wptr) wptr = d_in[2];
    if (!mptr) mptr = d_in[3];

    int B = 0;
    for (int i = 0; i < n_in; i++)
        if (in_sizes[i] >= (1 << 20)) { B = in_sizes[i] / (A_DIM * F_DIM); break; }
    if (!B) B = 4096;

    int dev = 0, sms = 148;
    cudaGetDevice(&dev);
    cudaDeviceGetAttribute(&sms, cudaDevAttrMultiProcessorCount, dev);
    cudaFuncSetAttribute(blockend_mma, cudaFuncAttributeMaxDynamicSharedMemorySize,
                         SMEM_TOTAL);

    int grid = sms < B ? sms : B;
    blockend_mma<<<grid, 512, SMEM_TOTAL>>>(node, res, (const float*)wptr,
                                            (const int*)mptr, (float*)d_out, B);
}